// round 1
// baseline (speedup 1.0000x reference)
#include <cuda_runtime.h>
#include <cfloat>
#include <math.h>

#define B_   16
#define NPER 2048
#define NTOT (B_*NPER)
#define KNN  20

// ---------------- scratch (device globals; no runtime allocation) ----------
__device__ float4 g_x0[NTOT];            // [N][4]  concat(pos, x)
__device__ int    g_idx[NTOT*KNN];       // [N][20] global neighbor indices
__device__ float  g_x1[NTOT*64];
__device__ float  g_x2[NTOT*64];
__device__ float  g_x3[NTOT*128];
__device__ float  g_out2[B_*1024];       // global max pool result

__device__ __forceinline__ void atomicMaxFloat(float* addr, float v){
    if (v >= 0.f) atomicMax((int*)addr, __float_as_int(v));
    else          atomicMin((unsigned int*)addr, (unsigned int)__float_as_int(v));
}

// ---------------- kNN: one thread per query node ---------------------------
__global__ __launch_bounds__(256) void knn_kernel(const float* __restrict__ pos,
                                                  const float* __restrict__ xf)
{
    __shared__ float4 sp[NPER];
    __shared__ float  sn[NPER];
    int b     = blockIdx.x >> 3;
    int qbase = (blockIdx.x & 7) << 8;
    int base  = b * NPER;
    for (int j = threadIdx.x; j < NPER; j += 256){
        float px = pos[(base+j)*3+0];
        float py = pos[(base+j)*3+1];
        float pz = pos[(base+j)*3+2];
        float pw = xf[base+j];
        float4 p = make_float4(px,py,pz,pw);
        sp[j] = p;
        sn[j] = px*px + py*py + pz*pz + pw*pw;
        if ((blockIdx.x & 7) == 0) g_x0[base+j] = p;   // write x0 once per graph
    }
    __syncthreads();

    int q = qbase + (int)threadIdx.x;
    float4 p = sp[q];
    float  pn = sn[q];
    float bd[KNN]; int bi[KNN];
    #pragma unroll
    for (int t=0;t<KNN;t++){ bd[t]=FLT_MAX; bi[t]=0; }
    float worst = FLT_MAX; int ws = 0;

    for (int j=0;j<NPER;j++){
        float4 c = sp[j];
        float d = pn + sn[j] - 2.f*(p.x*c.x + p.y*c.y + p.z*c.z + p.w*c.w);
        if (d < worst && j != q){
            bd[ws] = d; bi[ws] = j;
            worst = bd[0]; ws = 0;
            #pragma unroll
            for (int t=1;t<KNN;t++) if (bd[t] > worst){ worst = bd[t]; ws = t; }
        }
    }
    #pragma unroll
    for (int t=0;t<KNN;t++) g_idx[(base+q)*KNN + t] = base + bi[t];
}

// ---------------- EdgeConv1: fused MLP(8->64->64->64), max over K ----------
// h1 = relu(b1 + x_i*(W1top-W1bot) + x_j*W1bot); h2 = relu(b2 + h1*W2); h3 = b3 + h2*W3
__global__ __launch_bounds__(128) void conv1_kernel(
    const float* __restrict__ w1, const float* __restrict__ b1,
    const float* __restrict__ w2, const float* __restrict__ b2,
    const float* __restrict__ w3, const float* __restrict__ b3)
{
    __shared__ float sW1 [4*64];     // bottom rows of w1
    __shared__ float sW1d[4*64];     // top - bottom
    __shared__ float sW2t[64*68];    // transposed, padded (stride 68 -> conflict-free LDS.128)
    __shared__ float sW3t[64*68];
    __shared__ float sb1[64], sb2[64], sb3[64];
    __shared__ float h1buf[4][4][64];
    __shared__ float h2buf[4][4][64];

    for (int t = threadIdx.x; t < 64*64; t += 128){
        int c = t >> 6, o = t & 63;
        sW2t[o*68+c] = w2[t];
        sW3t[o*68+c] = w3[t];
    }
    for (int t = threadIdx.x; t < 4*64; t += 128){
        int c = t >> 6, o = t & 63;
        float top = w1[c*64+o], bot = w1[(c+4)*64+o];
        sW1[t] = bot; sW1d[t] = top - bot;
    }
    if (threadIdx.x < 64){
        sb1[threadIdx.x] = b1[threadIdx.x];
        sb2[threadIdx.x] = b2[threadIdx.x];
        sb3[threadIdx.x] = b3[threadIdx.x];
    }
    __syncthreads();

    int wd = threadIdx.x >> 5, lane = threadIdx.x & 31;
    int i  = blockIdx.x * 4 + wd;
    int o0 = lane, o1 = lane + 32;
    float4 xi = g_x0[i];
    float base0 = sb1[o0] + xi.x*sW1d[o0] + xi.y*sW1d[64+o0] + xi.z*sW1d[128+o0] + xi.w*sW1d[192+o0];
    float base1 = sb1[o1] + xi.x*sW1d[o1] + xi.y*sW1d[64+o1] + xi.z*sW1d[128+o1] + xi.w*sW1d[192+o1];
    float mx0 = -FLT_MAX, mx1 = -FLT_MAX;
    const int* ip = g_idx + i*KNN;

    for (int kg = 0; kg < 5; kg++){
        #pragma unroll
        for (int e=0;e<4;e++){
            int j = ip[kg*4+e];
            float4 xj = g_x0[j];
            float v0 = base0 + xj.x*sW1[o0] + xj.y*sW1[64+o0] + xj.z*sW1[128+o0] + xj.w*sW1[192+o0];
            float v1 = base1 + xj.x*sW1[o1] + xj.y*sW1[64+o1] + xj.z*sW1[128+o1] + xj.w*sW1[192+o1];
            h1buf[wd][e][o0] = fmaxf(v0, 0.f);
            h1buf[wd][e][o1] = fmaxf(v1, 0.f);
        }
        __syncwarp();
        float a0[4], a1[4];
        #pragma unroll
        for (int e=0;e<4;e++){ a0[e]=sb2[o0]; a1[e]=sb2[o1]; }
        #pragma unroll
        for (int c4=0;c4<16;c4++){
            float4 wv0 = *(const float4*)(sW2t + o0*68 + c4*4);
            float4 wv1 = *(const float4*)(sW2t + o1*68 + c4*4);
            #pragma unroll
            for (int e=0;e<4;e++){
                float4 h = *(const float4*)(&h1buf[wd][e][c4*4]);
                a0[e] += h.x*wv0.x + h.y*wv0.y + h.z*wv0.z + h.w*wv0.w;
                a1[e] += h.x*wv1.x + h.y*wv1.y + h.z*wv1.z + h.w*wv1.w;
            }
        }
        __syncwarp();
        #pragma unroll
        for (int e=0;e<4;e++){
            h2buf[wd][e][o0] = fmaxf(a0[e], 0.f);
            h2buf[wd][e][o1] = fmaxf(a1[e], 0.f);
        }
        __syncwarp();
        #pragma unroll
        for (int e=0;e<4;e++){ a0[e]=sb3[o0]; a1[e]=sb3[o1]; }
        #pragma unroll
        for (int c4=0;c4<16;c4++){
            float4 wv0 = *(const float4*)(sW3t + o0*68 + c4*4);
            float4 wv1 = *(const float4*)(sW3t + o1*68 + c4*4);
            #pragma unroll
            for (int e=0;e<4;e++){
                float4 h = *(const float4*)(&h2buf[wd][e][c4*4]);
                a0[e] += h.x*wv0.x + h.y*wv0.y + h.z*wv0.z + h.w*wv0.w;
                a1[e] += h.x*wv1.x + h.y*wv1.y + h.z*wv1.z + h.w*wv1.w;
            }
        }
        #pragma unroll
        for (int e=0;e<4;e++){ mx0 = fmaxf(mx0, a0[e]); mx1 = fmaxf(mx1, a1[e]); }
        __syncwarp();
    }
    g_x1[i*64+o0] = mx0;
    g_x1[i*64+o1] = mx1;
}

// ---------------- EdgeConv2: 128->64 single layer, max over K --------------
__global__ __launch_bounds__(128) void conv2_kernel(
    const float* __restrict__ w, const float* __restrict__ bias)
{
    __shared__ float sWtt[64*68], sWbt[64*68];
    __shared__ float sb[64];
    __shared__ float xjbuf[4][4][64];
    __shared__ float xibuf[4][64];
    for (int t = threadIdx.x; t < 64*64; t += 128){
        int c = t >> 6, o = t & 63;
        sWtt[o*68+c] = w[t];
        sWbt[o*68+c] = w[4096 + t];
    }
    if (threadIdx.x < 64) sb[threadIdx.x] = bias[threadIdx.x];
    __syncthreads();

    int wd = threadIdx.x >> 5, lane = threadIdx.x & 31;
    int i  = blockIdx.x*4 + wd;
    int o0 = lane, o1 = lane+32;
    xibuf[wd][o0] = g_x1[i*64+o0];
    xibuf[wd][o1] = g_x1[i*64+o1];
    __syncwarp();
    float base0 = sb[o0], base1 = sb[o1];
    #pragma unroll
    for (int c4=0;c4<16;c4++){
        float4 x4  = *(const float4*)(&xibuf[wd][c4*4]);
        float4 wt0 = *(const float4*)(sWtt + o0*68 + c4*4);
        float4 wb0 = *(const float4*)(sWbt + o0*68 + c4*4);
        float4 wt1 = *(const float4*)(sWtt + o1*68 + c4*4);
        float4 wb1 = *(const float4*)(sWbt + o1*68 + c4*4);
        base0 += x4.x*(wt0.x-wb0.x) + x4.y*(wt0.y-wb0.y) + x4.z*(wt0.z-wb0.z) + x4.w*(wt0.w-wb0.w);
        base1 += x4.x*(wt1.x-wb1.x) + x4.y*(wt1.y-wb1.y) + x4.z*(wt1.z-wb1.z) + x4.w*(wt1.w-wb1.w);
    }
    float mx0=-FLT_MAX, mx1=-FLT_MAX;
    const int* ip = g_idx + i*KNN;
    for (int kg=0;kg<5;kg++){
        #pragma unroll
        for (int e=0;e<4;e++){
            int j = ip[kg*4+e];
            xjbuf[wd][e][o0] = g_x1[j*64+o0];
            xjbuf[wd][e][o1] = g_x1[j*64+o1];
        }
        __syncwarp();
        float a0[4], a1[4];
        #pragma unroll
        for (int e=0;e<4;e++){ a0[e]=base0; a1[e]=base1; }
        #pragma unroll
        for (int c4=0;c4<16;c4++){
            float4 wv0 = *(const float4*)(sWbt + o0*68 + c4*4);
            float4 wv1 = *(const float4*)(sWbt + o1*68 + c4*4);
            #pragma unroll
            for (int e=0;e<4;e++){
                float4 h = *(const float4*)(&xjbuf[wd][e][c4*4]);
                a0[e] += h.x*wv0.x + h.y*wv0.y + h.z*wv0.z + h.w*wv0.w;
                a1[e] += h.x*wv1.x + h.y*wv1.y + h.z*wv1.z + h.w*wv1.w;
            }
        }
        #pragma unroll
        for (int e=0;e<4;e++){ mx0=fmaxf(mx0,a0[e]); mx1=fmaxf(mx1,a1[e]); }
        __syncwarp();
    }
    g_x2[i*64+o0]=mx0; g_x2[i*64+o1]=mx1;
}

// ---------------- EdgeConv3: 128->128 single layer, max over K -------------
__global__ __launch_bounds__(128) void conv3_kernel(
    const float* __restrict__ w, const float* __restrict__ bias)
{
    __shared__ float sWbt[128*68];
    __shared__ float sb[128];
    __shared__ float xjbuf[4][4][64];
    __shared__ float xibuf[4][64];
    for (int t = threadIdx.x; t < 64*128; t += 128){
        int c = t >> 7, o = t & 127;
        sWbt[o*68+c] = w[(64+c)*128 + o];
    }
    if (threadIdx.x < 128) sb[threadIdx.x] = bias[threadIdx.x];
    __syncthreads();

    int wd = threadIdx.x >> 5, lane = threadIdx.x & 31;
    int i  = blockIdx.x*4 + wd;
    xibuf[wd][lane]    = g_x2[i*64+lane];
    xibuf[wd][lane+32] = g_x2[i*64+lane+32];
    __syncwarp();
    float base[4];
    #pragma unroll
    for (int oo=0;oo<4;oo++) base[oo] = sb[lane+32*oo];
    for (int c4=0;c4<16;c4++){
        float4 x4 = *(const float4*)(&xibuf[wd][c4*4]);
        #pragma unroll
        for (int oo=0;oo<4;oo++){
            int o = lane+32*oo;
            float4 wb = *(const float4*)(sWbt + o*68 + c4*4);
            float t0 = __ldg(&w[(c4*4+0)*128+o]);
            float t1 = __ldg(&w[(c4*4+1)*128+o]);
            float t2 = __ldg(&w[(c4*4+2)*128+o]);
            float t3 = __ldg(&w[(c4*4+3)*128+o]);
            base[oo] += x4.x*(t0-wb.x) + x4.y*(t1-wb.y) + x4.z*(t2-wb.z) + x4.w*(t3-wb.w);
        }
    }
    float mx[4] = {-FLT_MAX,-FLT_MAX,-FLT_MAX,-FLT_MAX};
    const int* ip = g_idx + i*KNN;
    for (int kg=0;kg<5;kg++){
        #pragma unroll
        for (int e=0;e<4;e++){
            int j = ip[kg*4+e];
            xjbuf[wd][e][lane]    = g_x2[j*64+lane];
            xjbuf[wd][e][lane+32] = g_x2[j*64+lane+32];
        }
        __syncwarp();
        float acc[4][4];
        #pragma unroll
        for (int e=0;e<4;e++)
            #pragma unroll
            for (int oo=0;oo<4;oo++) acc[e][oo]=base[oo];
        for (int c4=0;c4<16;c4++){
            float4 wv[4];
            #pragma unroll
            for (int oo=0;oo<4;oo++) wv[oo] = *(const float4*)(sWbt + (lane+32*oo)*68 + c4*4);
            #pragma unroll
            for (int e=0;e<4;e++){
                float4 h = *(const float4*)(&xjbuf[wd][e][c4*4]);
                #pragma unroll
                for (int oo=0;oo<4;oo++)
                    acc[e][oo] += h.x*wv[oo].x + h.y*wv[oo].y + h.z*wv[oo].z + h.w*wv[oo].w;
            }
        }
        #pragma unroll
        for (int e=0;e<4;e++)
            #pragma unroll
            for (int oo=0;oo<4;oo++) mx[oo] = fmaxf(mx[oo], acc[e][oo]);
        __syncwarp();
    }
    #pragma unroll
    for (int oo=0;oo<4;oo++) g_x3[i*128 + lane + 32*oo] = mx[oo];
}

// ---------------- init pool buffer ------------------------------------------
__global__ void init_out2_kernel(){
    int t = blockIdx.x*blockDim.x + threadIdx.x;
    if (t < B_*1024) g_out2[t] = -FLT_MAX;
}

// ---------------- lin1 (256->1024) fused with global max pool --------------
__global__ __launch_bounds__(256) void lin1max_kernel(
    const float* __restrict__ l1w, const float* __restrict__ l1b)
{
    __shared__ float fbuf[64*33];
    __shared__ float wbuf[32*132];
    int g     = blockIdx.x >> 5;
    int nbase = g*NPER + (blockIdx.x & 31)*64;
    int tn = threadIdx.x & 15, to = threadIdx.x >> 4;

    for (int oc=0; oc<8; ++oc){
        float acc[4][8];
        #pragma unroll
        for (int r=0;r<4;r++)
            #pragma unroll
            for (int q=0;q<8;q++) acc[r][q]=0.f;

        for (int kc=0;kc<8;kc++){
            for (int t=threadIdx.x; t<64*32; t+=256){
                int n = t>>5, kk = t&31;
                int kglob = kc*32+kk;
                int node  = nbase + n;
                float v;
                if (kglob < 64)       v = g_x1[node*64  + kglob];
                else if (kglob < 128) v = g_x2[node*64  + (kglob-64)];
                else                  v = g_x3[node*128 + (kglob-128)];
                fbuf[n*33+kk] = v;
            }
            for (int t=threadIdx.x; t<32*128; t+=256){
                int kk = t>>7, o = t&127;
                wbuf[kk*132+o] = l1w[(kc*32+kk)*1024 + oc*128 + o];
            }
            __syncthreads();
            #pragma unroll 4
            for (int kk=0;kk<32;kk++){
                float f0 = fbuf[(tn*4+0)*33+kk];
                float f1 = fbuf[(tn*4+1)*33+kk];
                float f2 = fbuf[(tn*4+2)*33+kk];
                float f3 = fbuf[(tn*4+3)*33+kk];
                float wv[8];
                #pragma unroll
                for (int q=0;q<8;q++) wv[q] = wbuf[kk*132 + to*8 + q];
                #pragma unroll
                for (int q=0;q<8;q++){
                    acc[0][q] += f0*wv[q];
                    acc[1][q] += f1*wv[q];
                    acc[2][q] += f2*wv[q];
                    acc[3][q] += f3*wv[q];
                }
            }
            __syncthreads();
        }
        float m[8];
        #pragma unroll
        for (int q=0;q<8;q++)
            m[q] = fmaxf(fmaxf(acc[0][q],acc[1][q]), fmaxf(acc[2][q],acc[3][q]));
        #pragma unroll
        for (int q=0;q<8;q++) fbuf[tn*128 + to*8 + q] = m[q];
        __syncthreads();
        if (threadIdx.x < 128){
            int o = threadIdx.x;
            float v = fbuf[o];
            #pragma unroll
            for (int t=1;t<16;t++) v = fmaxf(v, fbuf[t*128+o]);
            v += l1b[oc*128+o];
            atomicMaxFloat(&g_out2[g*1024 + oc*128 + o], v);
        }
        __syncthreads();
    }
}

// ---------------- head: MLP(1024->512->256->10) + log_softmax --------------
__global__ __launch_bounds__(256) void head_kernel(
    const float* __restrict__ m1w, const float* __restrict__ m1b,
    const float* __restrict__ m2w, const float* __restrict__ m2b,
    const float* __restrict__ m3w, const float* __restrict__ m3b,
    float* __restrict__ out)
{
    __shared__ float v[1024];
    __shared__ float h1[512];
    __shared__ float h2[256];
    __shared__ float z[10];
    int g = blockIdx.x;
    for (int t=threadIdx.x; t<1024; t+=256) v[t] = g_out2[g*1024+t];
    __syncthreads();
    #pragma unroll
    for (int oo=0;oo<2;oo++){
        int o = threadIdx.x + oo*256;
        float a = m1b[o];
        #pragma unroll 4
        for (int k=0;k<1024;k++) a += v[k]*m1w[k*512+o];
        h1[o] = fmaxf(a, 0.f);
    }
    __syncthreads();
    {
        int o = threadIdx.x;
        float a = m2b[o];
        #pragma unroll 4
        for (int k=0;k<512;k++) a += h1[k]*m2w[k*256+o];
        h2[o] = fmaxf(a, 0.f);
    }
    __syncthreads();
    if (threadIdx.x < 10){
        float a = m3b[threadIdx.x];
        for (int k=0;k<256;k++) a += h2[k]*m3w[k*10+threadIdx.x];
        z[threadIdx.x] = a;
    }
    __syncthreads();
    if (threadIdx.x == 0){
        float m = -FLT_MAX;
        for (int c=0;c<10;c++) m = fmaxf(m, z[c]);
        float s = 0.f;
        for (int c=0;c<10;c++) s += expf(z[c]-m);
        float l = logf(s);
        for (int c=0;c<10;c++) out[g*10+c] = z[c]-m-l;
    }
}

// ---------------- launch ----------------------------------------------------
extern "C" void kernel_launch(void* const* d_in, const int* in_sizes, int n_in,
                              void* d_out, int out_size)
{
    const float* pos  = (const float*)d_in[0];
    const float* xf   = (const float*)d_in[1];
    // d_in[2] = batch (implied by layout, unused)
    const float* c1w1 = (const float*)d_in[3];
    const float* c1b1 = (const float*)d_in[4];
    const float* c1w2 = (const float*)d_in[5];
    const float* c1b2 = (const float*)d_in[6];
    const float* c1w3 = (const float*)d_in[7];
    const float* c1b3 = (const float*)d_in[8];
    const float* c2w  = (const float*)d_in[9];
    const float* c2b  = (const float*)d_in[10];
    const float* c3w  = (const float*)d_in[11];
    const float* c3b  = (const float*)d_in[12];
    const float* l1w  = (const float*)d_in[13];
    const float* l1b  = (const float*)d_in[14];
    const float* m1w  = (const float*)d_in[15];
    const float* m1b  = (const float*)d_in[16];
    const float* m2w  = (const float*)d_in[17];
    const float* m2b  = (const float*)d_in[18];
    const float* m3w  = (const float*)d_in[19];
    const float* m3b  = (const float*)d_in[20];
    float* out = (float*)d_out;

    knn_kernel<<<B_*8, 256>>>(pos, xf);
    conv1_kernel<<<NTOT/4, 128>>>(c1w1,c1b1,c1w2,c1b2,c1w3,c1b3);
    conv2_kernel<<<NTOT/4, 128>>>(c2w, c2b);
    conv3_kernel<<<NTOT/4, 128>>>(c3w, c3b);
    init_out2_kernel<<<(B_*1024+255)/256, 256>>>();
    lin1max_kernel<<<B_*32, 256>>>(l1w, l1b);
    head_kernel<<<B_, 256>>>(m1w,m1b,m2w,m2b,m3w,m3b,out);
}